// round 13
// baseline (speedup 1.0000x reference)
#include <cuda_runtime.h>
#include <stdint.h>

#define HW 16384   // 128*128

// ---- device scratch ----
__device__ float g_pool[4 * 8 * 128 * 15];   // [br][b][c][pos]
__device__ float g_Wfold[8 * 96 * 16];       // Whh @ W_center per group
__device__ float g_Gi[8 * 8 * 96 * 15];      // [b][g][o][pos] (includes bih)

// ---- helpers ----
// pack two f32 into f16x2: lower = first arg, upper = second arg
__device__ __forceinline__ uint32_t pack_h2(float lo, float hi) {
    uint32_t r; asm("cvt.rn.f16x2.f32 %0, %1, %2;" : "=r"(r) : "f"(hi), "f"(lo));
    return r;
}
__device__ __forceinline__ uint32_t htanh2(uint32_t x) {
    uint32_t y; asm("tanh.approx.f16x2 %0, %1;" : "=r"(y) : "r"(x)); return y;
}
__device__ __forceinline__ uint32_t hmul2_u(uint32_t a, uint32_t b) {
    uint32_t d; asm("mul.rn.f16x2 %0, %1, %2;" : "=r"(d) : "r"(a), "r"(b)); return d;
}
__device__ __forceinline__ uint32_t hfma2_u(uint32_t a, uint32_t b, uint32_t c) {
    uint32_t d; asm("fma.rn.f16x2 %0, %1, %2, %3;" : "=r"(d) : "r"(a), "r"(b), "r"(c));
    return d;
}
#define H05X2 0x38003800u   // {0.5h, 0.5h}
// sigmoid(x) = 0.5*tanh(0.5x)+0.5, packed
__device__ __forceinline__ uint32_t sig2_u(uint32_t x) {
    return hfma2_u(htanh2(hmul2_u(x, H05X2)), H05X2, H05X2);
}
__device__ __forceinline__ float2 h2f(uint32_t v) {
    float lo, hi;
    asm("{.reg .f16 l, h; mov.b32 {l, h}, %2; cvt.f32.f16 %0, l; cvt.f32.f16 %1, h;}"
        : "=f"(lo), "=f"(hi) : "r"(v));
    return make_float2(lo, hi);
}
__device__ __forceinline__ void mmaf16_acc(float d[4], const uint32_t a[4],
                                           uint32_t b0, uint32_t b1) {
    asm("mma.sync.aligned.m16n8k16.row.col.f32.f16.f16.f32 "
        "{%0,%1,%2,%3},{%4,%5,%6,%7},{%8,%9},{%0,%1,%2,%3};"
        : "+f"(d[0]), "+f"(d[1]), "+f"(d[2]), "+f"(d[3])
        : "r"(a[0]), "r"(a[1]), "r"(a[2]), "r"(a[3]), "r"(b0), "r"(b1));
}
__device__ __forceinline__ void mmaf16_init(float d[4], const uint32_t a[4],
                                            uint32_t b0, uint32_t b1,
                                            float c0, float c1) {
    asm("mma.sync.aligned.m16n8k16.row.col.f32.f16.f16.f32 "
        "{%0,%1,%2,%3},{%4,%5,%6,%7},{%8,%9},{%10,%11,%10,%11};"
        : "=f"(d[0]), "=f"(d[1]), "=f"(d[2]), "=f"(d[3])
        : "r"(a[0]), "r"(a[1]), "r"(a[2]), "r"(a[3]), "r"(b0), "r"(b1),
          "f"(c0), "f"(c1));
}
__device__ __forceinline__ float coef_f(int pos, int j0, float fw) {
    return (pos == j0) ? (1.0f - fw) : ((pos == j0 + 1) ? fw : 0.0f);
}

// ============================================================================
// K1: adaptive pools (proven R8 version). Block per (b,c), 256 threads =
// 2 per column (h halves); compile-time bin membership via full unroll.
// ============================================================================
#define POOL_BODY(hconst)                                                      \
    {                                                                          \
        const int hv = (hconst);                                               \
        float v = tile[hv * 128 + col];                                        \
        a0 += v;                                                               \
        {                                                                      \
            const int pb = (hv * 11) >> 7;                                     \
            a1[pb] += v;                                                       \
            if (pb + 1 < 11 && hv == ((pb + 1) * 128) / 11 &&                  \
                (((pb + 1) * 128) % 11) != 0) a1[pb + 1] += v;                 \
        }                                                                      \
        {                                                                      \
            const int pb = (hv * 3) >> 7;                                      \
            a2[pb] += v;                                                       \
            if (pb + 1 < 3 && hv == ((pb + 1) * 128) / 3 &&                    \
                (((pb + 1) * 128) % 3) != 0) a2[pb + 1] += v;                  \
        }                                                                      \
        {                                                                      \
            const int pb = (hv * 5) >> 7;                                      \
            a3[pb] += v;                                                       \
            if (pb + 1 < 5 && hv == ((pb + 1) * 128) / 5 &&                    \
                (((pb + 1) * 128) % 5) != 0) a3[pb + 1] += v;                  \
        }                                                                      \
    }

__global__ __launch_bounds__(256) void pool_kernel(const float* __restrict__ x) {
    const int bc = blockIdx.x;
    const int b = bc >> 7, c = bc & 127;
    const float* tile = x + (size_t)bc * HW;
    const int col = threadIdx.x & 127, hh = threadIdx.x >> 7;

    float a0 = 0.0f;
    float a1[11], a2[3], a3[5];
    #pragma unroll
    for (int i = 0; i < 11; i++) a1[i] = 0.0f;
    #pragma unroll
    for (int i = 0; i < 3; i++) a2[i] = 0.0f;
    #pragma unroll
    for (int i = 0; i < 5; i++) a3[i] = 0.0f;

    if (hh == 0) {
        #pragma unroll
        for (int h = 0; h < 64; h++) POOL_BODY(h)
    } else {
        #pragma unroll
        for (int h = 64; h < 128; h++) POOL_BODY(h)
    }

    __shared__ float cs[2][20][128];
    cs[hh][0][col] = a0;
    #pragma unroll
    for (int i = 0; i < 11; i++) cs[hh][1 + i][col] = a1[i];
    #pragma unroll
    for (int i = 0; i < 3; i++) cs[hh][12 + i][col] = a2[i];
    #pragma unroll
    for (int i = 0; i < 5; i++) cs[hh][15 + i][col] = a3[i];
    __syncthreads();

    const int warp = threadIdx.x >> 5, lane = threadIdx.x & 31;
    for (int oi = warp; oi < 52; oi += 8) {
        int br, pos, row, ws, we, hs, he;
        if (oi < 11) {
            br = 0; pos = oi; row = 0;
            hs = 0; he = 128;
            ws = (pos * 128) / 11; we = ((pos + 1) * 128 + 10) / 11;
        } else if (oi < 22) {
            br = 1; pos = oi - 11; row = 1 + pos;
            ws = 0; we = 128;
            hs = (pos * 128) / 11; he = ((pos + 1) * 128 + 10) / 11;
        } else if (oi < 37) {
            br = 2; pos = oi - 22;
            int i = pos / 5, jj = pos % 5;
            row = 12 + i;
            hs = (i * 128) / 3;  he = ((i + 1) * 128 + 2) / 3;
            ws = (jj * 128) / 5; we = ((jj + 1) * 128 + 4) / 5;
        } else {
            br = 3; pos = oi - 37;
            int i = pos / 3, jj = pos % 3;
            row = 15 + i;
            hs = (i * 128) / 5;  he = ((i + 1) * 128 + 4) / 5;
            ws = (jj * 128) / 3; we = ((jj + 1) * 128 + 2) / 3;
        }
        float s = 0.0f;
        for (int w = ws + lane; w < we; w += 32)
            s += cs[0][row][w] + cs[1][row][w];
        #pragma unroll
        for (int off = 16; off; off >>= 1) s += __shfl_down_sync(0xffffffffu, s, off);
        if (lane == 0)
            g_pool[((br * 8 + b) * 128 + c) * 15 + pos] =
                s / (float)((he - hs) * (we - ws));
    }
}

// ============================================================================
// K2: fused branch-linear + merge + Wih -> Gi (blocks 0..255, 4 per (b,g)),
//     plus Wfold = Whh @ W_center (blocks 256..263).
// ============================================================================
__global__ __launch_bounds__(256) void gi_fold_kernel(
    const float* __restrict__ W0, const float* __restrict__ b0,
    const float* __restrict__ W1, const float* __restrict__ b1,
    const float* __restrict__ W2, const float* __restrict__ b2,
    const float* __restrict__ W3, const float* __restrict__ b3,
    const float* __restrict__ Wm, const float* __restrict__ Wih,
    const float* __restrict__ bih,
    const float* __restrict__ Whh, const float* __restrict__ Wcen)
{
    const int blk = blockIdx.x;
    const int t = threadIdx.x;

    if (blk >= 256) {              // fold part
        int g = blk - 256;
        if (t < 96) {
            int o = t;
            #pragma unroll 4
            for (int i = 0; i < 16; i++) {
                float s = 0.0f;
                #pragma unroll
                for (int hh = 0; hh < 32; hh++)
                    s = fmaf(Whh[(g * 96 + o) * 32 + hh], Wcen[(g * 32 + hh) * 16 + i], s);
                g_Wfold[(g * 96 + o) * 16 + i] = s;
            }
        }
        return;
    }

    const int b = blk >> 5, g = (blk >> 2) & 7, quarter = blk & 3;
    const int br = g >> 1;
    const int GS = (br < 2) ? 11 : 15;
    const float* Ws[4] = {W0, W1, W2, W3};
    const float* bs[4] = {b0, b1, b2, b3};
    const float* W = Ws[br];
    const float* bias = bs[br];
    const int c0 = 64 * (g & 1);

    __shared__ float q[64 * 15];
    __shared__ float Bs[32 * 15];

    for (int idx = t; idx < 64 * GS; idx += 256) {
        int cc = idx / GS, m = idx - cc * GS;
        const float* src = g_pool + ((br * 8 + b) * 128 + c0 + cc) * 15;
        float s = bias[m];
        for (int d = 0; d < GS; d++) s = fmaf(W[m * GS + d], src[d], s);
        q[cc * GS + m] = s;
    }
    __syncthreads();

    for (int idx = t; idx < 32 * GS; idx += 256) {
        int f = idx / GS, pos = idx - f * GS;
        int i = 16 * g + (f >> 1), jm = f & 1;
        const float* qb = q + (4 * (f >> 1)) * GS + pos;
        float s = 0.0f;
        #pragma unroll
        for (int k = 0; k < 4; k++)
            s = fmaf(Wm[(i * 2 + jm) * 4 + k], qb[k * GS], s);
        Bs[f * GS + pos] = s;
    }
    __syncthreads();

    const int obase = quarter * 24;
    for (int idx = t; idx < 24 * GS; idx += 256) {
        int o = obase + idx / GS, pos = idx % GS;
        float s = bih[g * 96 + o];
        #pragma unroll 8
        for (int f = 0; f < 32; f++)
            s = fmaf(Wih[(g * 96 + o) * 32 + f], Bs[f * GS + pos], s);
        g_Gi[((b * 8 + g) * 96 + o) * 15 + pos] = s;
    }
}

// ============================================================================
// K3: main kernel (R8 structure; f16x2-packed activations in the epilogue).
// fp16 m16n8k16 mma; w-interp folded as extra k16 mma; direct-LDG A frags.
// grid (256, 8): g = blockIdx.y; b = blockIdx.x>>5; warp = one image row.
// ============================================================================
template<int OH, int OW>
__device__ __forceinline__ void run_group(
    int g, int b, const float* __restrict__ x, const float* __restrict__ bhh,
    float* __restrict__ out, const uint2* Wh, char* gbuf_raw)
{
    const int t = threadIdx.x;
    const int warp = t >> 5, lane = t & 31;
    const int p = lane >> 2, q = lane & 3;
    const int h = ((blockIdx.x & 31) << 2) + warp;
    const float* gib = g_Gi + (size_t)((b * 8 + g) * 96) * 15;

    // ---- build interp structures ----
    if (OW == 1) {
        float* gw = (float*)gbuf_raw + warp * 96;
        float src = (float)(h * (OH - 1)) * (1.0f / 127.0f);
        int ih0 = (int)src; if (ih0 > OH - 2) ih0 = OH - 2;
        float fh = src - (float)ih0;
        for (int j = lane; j < 96; j += 32) {
            float v0 = gib[j * 15 + ih0];
            float v1 = gib[j * 15 + ih0 + 1];
            float v = fmaf(fh, v1 - v0, v0);
            if (j < 64) v += bhh[g * 96 + j];
            gw[j] = v;
        }
    } else if (OH == 1) {
        uint2* gp = (uint2*)gbuf_raw;
        for (int idx = t; idx < 384; idx += 128) {
            int j = idx & 31, Gq = idx >> 5;
            int G = Gq >> 2, qq = Gq & 3;
            int jg = G * 32 + j;
            float bv = (G < 2) ? bhh[g * 96 + jg] : 0.0f;
            float v0 = (2 * qq     < OW) ? gib[jg * 15 + 2 * qq]     + bv : 0.0f;
            float v1 = (2 * qq + 1 < OW) ? gib[jg * 15 + 2 * qq + 1] + bv : 0.0f;
            float v2 = (2 * qq + 8 < OW) ? gib[jg * 15 + 2 * qq + 8] + bv : 0.0f;
            float v3 = (2 * qq + 9 < OW) ? gib[jg * 15 + 2 * qq + 9] + bv : 0.0f;
            gp[Gq * 36 + j] = make_uint2(pack_h2(v0, v1), pack_h2(v2, v3));
        }
    } else {
        uint2* gp = (uint2*)gbuf_raw + warp * 432;
        float src = (float)(h * (OH - 1)) * (1.0f / 127.0f);
        int ih0 = (int)src; if (ih0 > OH - 2) ih0 = OH - 2;
        float fh = src - (float)ih0;
        for (int idx = lane; idx < 384; idx += 32) {
            int j = idx & 31, Gq = idx >> 5;
            int G = Gq >> 2, qq = Gq & 3;
            int jg = G * 32 + j;
            float bv = (G < 2) ? bhh[g * 96 + jg] : 0.0f;
            float vv[4];
            const int pos[4] = {2 * qq, 2 * qq + 1, 2 * qq + 8, 2 * qq + 9};
            #pragma unroll
            for (int k2 = 0; k2 < 4; k2++) {
                float vx = 0.0f;
                if (pos[k2] < OW) {
                    float v0 = gib[jg * 15 + ih0 * OW + pos[k2]];
                    float v1 = gib[jg * 15 + (ih0 + 1) * OW + pos[k2]];
                    vx = fmaf(fh, v1 - v0, v0) + bv;
                }
                vv[k2] = vx;
            }
            gp[Gq * 36 + j] = make_uint2(pack_h2(vv[0], vv[1]), pack_h2(vv[2], vv[3]));
        }
    }
    __syncthreads();

    const uint2* gpB = (OH == 1) ? (const uint2*)gbuf_raw
                                 : ((const uint2*)gbuf_raw + warp * 432);

    // OW==1: row-constant gi values in registers
    float gvr[2][2][2], gvz[2][2][2], gvn[2][2][2];
    if (OW == 1) {
        const float* gw = (const float*)gbuf_raw + warp * 96;
        #pragma unroll
        for (int e = 0; e < 2; e++)
            #pragma unroll
            for (int u = 0; u < 2; u++)
                #pragma unroll
                for (int d = 0; d < 2; d++) {
                    int jl = 16 * e + 8 * u + 2 * q + d;
                    gvr[e][u][d] = gw[jl];
                    gvz[e][u][d] = gw[32 + jl];
                    gvn[e][u][d] = gw[64 + jl];
                }
    }

    // bhh_n pairs for hn C-init
    float bn[2][2][2];
    #pragma unroll
    for (int e = 0; e < 2; e++)
        #pragma unroll
        for (int u = 0; u < 2; u++) {
            bn[e][u][0] = bhh[g * 96 + 64 + 16 * e + 8 * u + 2 * q];
            bn[e][u][1] = bhh[g * 96 + 64 + 16 * e + 8 * u + 2 * q + 1];
        }

    const float* xrow = x + ((size_t)(b * 128 + g * 16)) * HW + h * 128;
    float* outrow = out + ((size_t)b * 256 + g) * HW + h * 128;
    const float* xc0 = xrow + (size_t)(2 * q) * HW;
    const float* xc1 = xrow + (size_t)(2 * q + 1) * HW;
    const float* xc2 = xrow + (size_t)(2 * q + 8) * HW;
    const float* xc3 = xrow + (size_t)(2 * q + 9) * HW;

    for (int tile2 = 0; tile2 < 4; tile2++) {
        const int pxbase = tile2 * 32;

        // ---- A fragments: direct loads, fp16-packed ----
        uint32_t A[2][4];
        #pragma unroll
        for (int m = 0; m < 2; m++) {
            const int p0 = pxbase + m * 16 + p;
            float x00 = xc0[p0],     x10 = xc1[p0];
            float x01 = xc0[p0 + 8], x11 = xc1[p0 + 8];
            float x20 = xc2[p0],     x30 = xc3[p0];
            float x21 = xc2[p0 + 8], x31 = xc3[p0 + 8];
            A[m][0] = pack_h2(x00, x10);
            A[m][1] = pack_h2(x01, x11);
            A[m][2] = pack_h2(x20, x30);
            A[m][3] = pack_h2(x21, x31);
        }

        // ---- coef fragments ----
        uint32_t AC[2][4];
        if (OW > 1) {
            #pragma unroll
            for (int m = 0; m < 2; m++) {
                const int pe0 = pxbase + m * 16 + p, pe1 = pe0 + 8;
                float s0 = (float)(pe0 * (OW - 1)) * (1.0f / 127.0f);
                int j00 = (int)s0; if (j00 > OW - 2) j00 = OW - 2;
                float f0 = s0 - (float)j00;
                float s1 = (float)(pe1 * (OW - 1)) * (1.0f / 127.0f);
                int j01 = (int)s1; if (j01 > OW - 2) j01 = OW - 2;
                float f1 = s1 - (float)j01;
                AC[m][0] = pack_h2(coef_f(2 * q, j00, f0),     coef_f(2 * q + 1, j00, f0));
                AC[m][1] = pack_h2(coef_f(2 * q, j01, f1),     coef_f(2 * q + 1, j01, f1));
                AC[m][2] = pack_h2(coef_f(2 * q + 8, j00, f0), coef_f(2 * q + 9, j00, f0));
                AC[m][3] = pack_h2(coef_f(2 * q + 8, j01, f1), coef_f(2 * q + 9, j01, f1));
            }
        }

        #pragma unroll
        for (int eta = 0; eta < 2; eta++) {
            #pragma unroll
            for (int u = 0; u < 2; u++) {
                const int cb = 16 * eta + 8 * u + p;
                uint2 wr = Wh[q * 132 + cb];
                uint2 wz = Wh[q * 132 + 32 + cb];
                uint2 wn = Wh[q * 132 + 64 + cb];
                uint2 wc = Wh[q * 132 + 96 + cb];
                uint2 grB, gzB, gnB;
                if (OW > 1) {
                    grB = gpB[(0 * 4 + q) * 36 + cb];
                    gzB = gpB[(1 * 4 + q) * 36 + cb];
                    gnB = gpB[(2 * 4 + q) * 36 + cb];
                }

                #pragma unroll
                for (int m = 0; m < 2; m++) {
                    float aR[4], aZ[4], aN[4], aC[4], aG[4];
                    mmaf16_init(aR, A[m], wr.x, wr.y, 0.f, 0.f);
                    mmaf16_init(aZ, A[m], wz.x, wz.y, 0.f, 0.f);
                    mmaf16_init(aN, A[m], wn.x, wn.y, bn[eta][u][0], bn[eta][u][1]);
                    mmaf16_init(aC, A[m], wc.x, wc.y, 0.f, 0.f);
                    if (OW > 1) {
                        mmaf16_acc(aR, AC[m], grB.x, grB.y);
                        mmaf16_acc(aZ, AC[m], gzB.x, gzB.y);
                        mmaf16_init(aG, AC[m], gnB.x, gnB.y, 0.f, 0.f);
                    }

                    // ---- packed f16x2 epilogue: pairs (d=0,1) per pixel e ----
                    #pragma unroll
                    for (int e = 0; e < 2; e++) {
                        const int i0 = 2 * e;
                        const int jl = 16 * eta + 8 * u + 2 * q;
                        const int px = pxbase + m * 16 + p + e * 8;
                        uint32_t r2, z2, gn2;
                        if (OW == 1) {
                            r2 = pack_h2(gvr[eta][u][0] + aR[i0],
                                         gvr[eta][u][1] + aR[i0 + 1]);
                            z2 = pack_h2(gvz[eta][u][0] + aZ[i0],
                                         gvz[eta][u][1] + aZ[i0 + 1]);
                            gn2 = pack_h2(gvn[eta][u][0], gvn[eta][u][1]);
                        } else {
                            r2 = pack_h2(aR[i0], aR[i0 + 1]);
                            z2 = pack_h2(aZ[i0], aZ[i0 + 1]);
                            gn2 = pack_h2(aG[i0], aG[i0 + 1]);
                        }
                        r2 = sig2_u(r2);
                        z2 = sig2_u(z2);
                        uint32_t hn2 = pack_h2(aN[i0], aN[i0 + 1]);
                        uint32_t n2 = htanh2(hfma2_u(r2, hn2, gn2));
                        float2 nf = h2f(n2);
                        float2 zf = h2f(z2);
                        outrow[(size_t)(jl * 8) * HW + px] =
                            fmaf(zf.x, aC[i0] - nf.x, nf.x);
                        outrow[(size_t)((jl + 1) * 8) * HW + px] =
                            fmaf(zf.y, aC[i0 + 1] - nf.y, nf.y);
                    }
                }
            }
        }
    }
}

__global__ __launch_bounds__(128, 5) void main_kernel(
    const float* __restrict__ x, const float* __restrict__ Wcen,
    const float* __restrict__ bhh, float* __restrict__ out)
{
    __shared__ __align__(16) uint2 Wh[4 * 132];        // fp16 weight k-pairs
    __shared__ __align__(16) char gbuf_raw[4 * 432 * 8];  // per-warp Gh / gw

    const int g = blockIdx.y;
    const int b = blockIdx.x >> 5;
    const int t = threadIdx.x;

    // build Wh: [q][col] uint2 with k = {2q,2q+1} and {2q+8,2q+9}
    for (int idx = t; idx < 512; idx += 128) {
        int qq = idx >> 7, col = idx & 127;
        float w0, w1, w2, w3;
        if (col < 96) {
            const float* wf = &g_Wfold[(g * 96 + col) * 16];
            w0 = wf[2 * qq];     w1 = wf[2 * qq + 1];
            w2 = wf[2 * qq + 8]; w3 = wf[2 * qq + 9];
        } else {
            const float* wf = &Wcen[(g * 32 + col - 96) * 16];
            w0 = wf[2 * qq];     w1 = wf[2 * qq + 1];
            w2 = wf[2 * qq + 8]; w3 = wf[2 * qq + 9];
        }
        Wh[qq * 132 + col] = make_uint2(pack_h2(w0, w1), pack_h2(w2, w3));
    }
    // (__syncthreads happens inside run_group after gbuf build)

    switch (g >> 1) {
        case 0:  run_group<1, 11>(g, b, x, bhh, out, Wh, gbuf_raw); break;
        case 1:  run_group<11, 1>(g, b, x, bhh, out, Wh, gbuf_raw); break;
        case 2:  run_group<3, 5>(g, b, x, bhh, out, Wh, gbuf_raw); break;
        default: run_group<5, 3>(g, b, x, bhh, out, Wh, gbuf_raw); break;
    }
}

// ============================================================================
extern "C" void kernel_launch(void* const* d_in, const int* in_sizes, int n_in,
                              void* d_out, int out_size) {
    (void)in_sizes; (void)n_in; (void)out_size;
    const float* x    = (const float*)d_in[0];
    const float* Wcen = (const float*)d_in[1];
    const float* W0 = (const float*)d_in[2];  const float* b0 = (const float*)d_in[3];
    const float* W1 = (const float*)d_in[4];  const float* b1 = (const float*)d_in[5];
    const float* W2 = (const float*)d_in[6];  const float* b2 = (const float*)d_in[7];
    const float* W3 = (const float*)d_in[8];  const float* b3 = (const float*)d_in[9];
    const float* Wm  = (const float*)d_in[10];
    const float* Wih = (const float*)d_in[11];
    const float* Whh = (const float*)d_in[12];
    const float* bih = (const float*)d_in[13];
    const float* bhh = (const float*)d_in[14];
    float* out = (float*)d_out;

    pool_kernel<<<1024, 256>>>(x);
    gi_fold_kernel<<<264, 256>>>(W0, b0, W1, b1, W2, b2, W3, b3,
                                 Wm, Wih, bih, Whh, Wcen);
    main_kernel<<<dim3(256, 8), 128>>>(x, Wcen, bhh, out);
}

// round 14
// speedup vs baseline: 1.3964x; 1.3964x over previous
#include <cuda_runtime.h>
#include <stdint.h>

#define HW 16384   // 128*128

// ---- device scratch ----
__device__ float g_pool[4 * 8 * 128 * 15];   // [br][b][c][pos]
__device__ float g_Wfold[8 * 96 * 16];       // Whh @ W_center per group
__device__ float g_Gi[8 * 8 * 96 * 15];      // [b][g][o][pos] (includes bih)

// ---- helpers ----
// pack two f32 into f16x2: lower = first arg, upper = second arg
__device__ __forceinline__ uint32_t pack_h2(float lo, float hi) {
    uint32_t r; asm("cvt.rn.f16x2.f32 %0, %1, %2;" : "=r"(r) : "f"(hi), "f"(lo));
    return r;
}
__device__ __forceinline__ uint32_t htanh2(uint32_t x) {
    uint32_t y; asm("tanh.approx.f16x2 %0, %1;" : "=r"(y) : "r"(x)); return y;
}
__device__ __forceinline__ uint32_t hmul2_u(uint32_t a, uint32_t b) {
    uint32_t d; asm("mul.rn.f16x2 %0, %1, %2;" : "=r"(d) : "r"(a), "r"(b)); return d;
}
__device__ __forceinline__ uint32_t hfma2_u(uint32_t a, uint32_t b, uint32_t c) {
    uint32_t d; asm("fma.rn.f16x2 %0, %1, %2, %3;" : "=r"(d) : "r"(a), "r"(b), "r"(c));
    return d;
}
#define H05X2 0x38003800u   // {0.5h, 0.5h}
// sigmoid(x) = 0.5*tanh(0.5x)+0.5, packed
__device__ __forceinline__ uint32_t sig2_u(uint32_t x) {
    return hfma2_u(htanh2(hmul2_u(x, H05X2)), H05X2, H05X2);
}
__device__ __forceinline__ float2 h2f(uint32_t v) {
    float lo, hi;
    asm("{.reg .f16 l, h; mov.b32 {l, h}, %2; cvt.f32.f16 %0, l; cvt.f32.f16 %1, h;}"
        : "=f"(lo), "=f"(hi) : "r"(v));
    return make_float2(lo, hi);
}
__device__ __forceinline__ void mmaf16_acc(float d[4], const uint32_t a[4],
                                           uint32_t b0, uint32_t b1) {
    asm("mma.sync.aligned.m16n8k16.row.col.f32.f16.f16.f32 "
        "{%0,%1,%2,%3},{%4,%5,%6,%7},{%8,%9},{%0,%1,%2,%3};"
        : "+f"(d[0]), "+f"(d[1]), "+f"(d[2]), "+f"(d[3])
        : "r"(a[0]), "r"(a[1]), "r"(a[2]), "r"(a[3]), "r"(b0), "r"(b1));
}
__device__ __forceinline__ void mmaf16_init(float d[4], const uint32_t a[4],
                                            uint32_t b0, uint32_t b1,
                                            float c0, float c1) {
    asm("mma.sync.aligned.m16n8k16.row.col.f32.f16.f16.f32 "
        "{%0,%1,%2,%3},{%4,%5,%6,%7},{%8,%9},{%10,%11,%10,%11};"
        : "=f"(d[0]), "=f"(d[1]), "=f"(d[2]), "=f"(d[3])
        : "r"(a[0]), "r"(a[1]), "r"(a[2]), "r"(a[3]), "r"(b0), "r"(b1),
          "f"(c0), "f"(c1));
}
__device__ __forceinline__ float coef_f(int pos, int j0, float fw) {
    return (pos == j0) ? (1.0f - fw) : ((pos == j0 + 1) ? fw : 0.0f);
}

// ============================================================================
// K1: adaptive pools (proven R8 version). Block per (b,c), 256 threads =
// 2 per column (h halves); compile-time bin membership via full unroll.
// ============================================================================
#define POOL_BODY(hconst)                                                      \
    {                                                                          \
        const int hv = (hconst);                                               \
        float v = tile[hv * 128 + col];                                        \
        a0 += v;                                                               \
        {                                                                      \
            const int pb = (hv * 11) >> 7;                                     \
            a1[pb] += v;                                                       \
            if (pb + 1 < 11 && hv == ((pb + 1) * 128) / 11 &&                  \
                (((pb + 1) * 128) % 11) != 0) a1[pb + 1] += v;                 \
        }                                                                      \
        {                                                                      \
            const int pb = (hv * 3) >> 7;                                      \
            a2[pb] += v;                                                       \
            if (pb + 1 < 3 && hv == ((pb + 1) * 128) / 3 &&                    \
                (((pb + 1) * 128) % 3) != 0) a2[pb + 1] += v;                  \
        }                                                                      \
        {                                                                      \
            const int pb = (hv * 5) >> 7;                                      \
            a3[pb] += v;                                                       \
            if (pb + 1 < 5 && hv == ((pb + 1) * 128) / 5 &&                    \
                (((pb + 1) * 128) % 5) != 0) a3[pb + 1] += v;                  \
        }                                                                      \
    }

__global__ __launch_bounds__(256) void pool_kernel(const float* __restrict__ x) {
    const int bc = blockIdx.x;
    const int b = bc >> 7, c = bc & 127;
    const float* tile = x + (size_t)bc * HW;
    const int col = threadIdx.x & 127, hh = threadIdx.x >> 7;

    float a0 = 0.0f;
    float a1[11], a2[3], a3[5];
    #pragma unroll
    for (int i = 0; i < 11; i++) a1[i] = 0.0f;
    #pragma unroll
    for (int i = 0; i < 3; i++) a2[i] = 0.0f;
    #pragma unroll
    for (int i = 0; i < 5; i++) a3[i] = 0.0f;

    if (hh == 0) {
        #pragma unroll
        for (int h = 0; h < 64; h++) POOL_BODY(h)
    } else {
        #pragma unroll
        for (int h = 64; h < 128; h++) POOL_BODY(h)
    }

    __shared__ float cs[2][20][128];
    cs[hh][0][col] = a0;
    #pragma unroll
    for (int i = 0; i < 11; i++) cs[hh][1 + i][col] = a1[i];
    #pragma unroll
    for (int i = 0; i < 3; i++) cs[hh][12 + i][col] = a2[i];
    #pragma unroll
    for (int i = 0; i < 5; i++) cs[hh][15 + i][col] = a3[i];
    __syncthreads();

    const int warp = threadIdx.x >> 5, lane = threadIdx.x & 31;
    for (int oi = warp; oi < 52; oi += 8) {
        int br, pos, row, ws, we, hs, he;
        if (oi < 11) {
            br = 0; pos = oi; row = 0;
            hs = 0; he = 128;
            ws = (pos * 128) / 11; we = ((pos + 1) * 128 + 10) / 11;
        } else if (oi < 22) {
            br = 1; pos = oi - 11; row = 1 + pos;
            ws = 0; we = 128;
            hs = (pos * 128) / 11; he = ((pos + 1) * 128 + 10) / 11;
        } else if (oi < 37) {
            br = 2; pos = oi - 22;
            int i = pos / 5, jj = pos % 5;
            row = 12 + i;
            hs = (i * 128) / 3;  he = ((i + 1) * 128 + 2) / 3;
            ws = (jj * 128) / 5; we = ((jj + 1) * 128 + 4) / 5;
        } else {
            br = 3; pos = oi - 37;
            int i = pos / 3, jj = pos % 3;
            row = 15 + i;
            hs = (i * 128) / 5;  he = ((i + 1) * 128 + 4) / 5;
            ws = (jj * 128) / 3; we = ((jj + 1) * 128 + 2) / 3;
        }
        float s = 0.0f;
        for (int w = ws + lane; w < we; w += 32)
            s += cs[0][row][w] + cs[1][row][w];
        #pragma unroll
        for (int off = 16; off; off >>= 1) s += __shfl_down_sync(0xffffffffu, s, off);
        if (lane == 0)
            g_pool[((br * 8 + b) * 128 + c) * 15 + pos] =
                s / (float)((he - hs) * (we - ws));
    }
}

// ============================================================================
// K2: fused branch-linear + merge + Wih -> Gi (blocks 0..255, 4 per (b,g)),
//     plus Wfold = Whh @ W_center (blocks 256..263).
// ============================================================================
__global__ __launch_bounds__(256) void gi_fold_kernel(
    const float* __restrict__ W0, const float* __restrict__ b0,
    const float* __restrict__ W1, const float* __restrict__ b1,
    const float* __restrict__ W2, const float* __restrict__ b2,
    const float* __restrict__ W3, const float* __restrict__ b3,
    const float* __restrict__ Wm, const float* __restrict__ Wih,
    const float* __restrict__ bih,
    const float* __restrict__ Whh, const float* __restrict__ Wcen)
{
    const int blk = blockIdx.x;
    const int t = threadIdx.x;

    if (blk >= 256) {              // fold part
        int g = blk - 256;
        if (t < 96) {
            int o = t;
            #pragma unroll 4
            for (int i = 0; i < 16; i++) {
                float s = 0.0f;
                #pragma unroll
                for (int hh = 0; hh < 32; hh++)
                    s = fmaf(Whh[(g * 96 + o) * 32 + hh], Wcen[(g * 32 + hh) * 16 + i], s);
                g_Wfold[(g * 96 + o) * 16 + i] = s;
            }
        }
        return;
    }

    const int b = blk >> 5, g = (blk >> 2) & 7, quarter = blk & 3;
    const int br = g >> 1;
    const int GS = (br < 2) ? 11 : 15;
    const float* Ws[4] = {W0, W1, W2, W3};
    const float* bs[4] = {b0, b1, b2, b3};
    const float* W = Ws[br];
    const float* bias = bs[br];
    const int c0 = 64 * (g & 1);

    __shared__ float q[64 * 15];
    __shared__ float Bs[32 * 15];

    for (int idx = t; idx < 64 * GS; idx += 256) {
        int cc = idx / GS, m = idx - cc * GS;
        const float* src = g_pool + ((br * 8 + b) * 128 + c0 + cc) * 15;
        float s = bias[m];
        for (int d = 0; d < GS; d++) s = fmaf(W[m * GS + d], src[d], s);
        q[cc * GS + m] = s;
    }
    __syncthreads();

    for (int idx = t; idx < 32 * GS; idx += 256) {
        int f = idx / GS, pos = idx - f * GS;
        int i = 16 * g + (f >> 1), jm = f & 1;
        const float* qb = q + (4 * (f >> 1)) * GS + pos;
        float s = 0.0f;
        #pragma unroll
        for (int k = 0; k < 4; k++)
            s = fmaf(Wm[(i * 2 + jm) * 4 + k], qb[k * GS], s);
        Bs[f * GS + pos] = s;
    }
    __syncthreads();

    const int obase = quarter * 24;
    for (int idx = t; idx < 24 * GS; idx += 256) {
        int o = obase + idx / GS, pos = idx % GS;
        float s = bih[g * 96 + o];
        #pragma unroll 8
        for (int f = 0; f < 32; f++)
            s = fmaf(Wih[(g * 96 + o) * 32 + f], Bs[f * GS + pos], s);
        g_Gi[((b * 8 + g) * 96 + o) * 15 + pos] = s;
    }
}

// ============================================================================
// K3: main kernel (R8 structure; f16x2-packed activations in the epilogue).
// fp16 m16n8k16 mma; w-interp folded as extra k16 mma; direct-LDG A frags.
// grid (256, 8): g = blockIdx.y; b = blockIdx.x>>5; warp = one image row.
// ============================================================================
template<int OH, int OW>
__device__ __forceinline__ void run_group(
    int g, int b, const float* __restrict__ x, const float* __restrict__ bhh,
    float* __restrict__ out, const uint2* Wh, char* gbuf_raw)
{
    const int t = threadIdx.x;
    const int warp = t >> 5, lane = t & 31;
    const int p = lane >> 2, q = lane & 3;
    const int h = ((blockIdx.x & 31) << 2) + warp;
    const float* gib = g_Gi + (size_t)((b * 8 + g) * 96) * 15;

    // ---- build interp structures ----
    if (OW == 1) {
        float* gw = (float*)gbuf_raw + warp * 96;
        float src = (float)(h * (OH - 1)) * (1.0f / 127.0f);
        int ih0 = (int)src; if (ih0 > OH - 2) ih0 = OH - 2;
        float fh = src - (float)ih0;
        for (int j = lane; j < 96; j += 32) {
            float v0 = gib[j * 15 + ih0];
            float v1 = gib[j * 15 + ih0 + 1];
            float v = fmaf(fh, v1 - v0, v0);
            if (j < 64) v += bhh[g * 96 + j];
            gw[j] = v;
        }
    } else if (OH == 1) {
        uint2* gp = (uint2*)gbuf_raw;
        for (int idx = t; idx < 384; idx += 128) {
            int j = idx & 31, Gq = idx >> 5;
            int G = Gq >> 2, qq = Gq & 3;
            int jg = G * 32 + j;
            float bv = (G < 2) ? bhh[g * 96 + jg] : 0.0f;
            float v0 = (2 * qq     < OW) ? gib[jg * 15 + 2 * qq]     + bv : 0.0f;
            float v1 = (2 * qq + 1 < OW) ? gib[jg * 15 + 2 * qq + 1] + bv : 0.0f;
            float v2 = (2 * qq + 8 < OW) ? gib[jg * 15 + 2 * qq + 8] + bv : 0.0f;
            float v3 = (2 * qq + 9 < OW) ? gib[jg * 15 + 2 * qq + 9] + bv : 0.0f;
            gp[Gq * 36 + j] = make_uint2(pack_h2(v0, v1), pack_h2(v2, v3));
        }
    } else {
        uint2* gp = (uint2*)gbuf_raw + warp * 432;
        float src = (float)(h * (OH - 1)) * (1.0f / 127.0f);
        int ih0 = (int)src; if (ih0 > OH - 2) ih0 = OH - 2;
        float fh = src - (float)ih0;
        for (int idx = lane; idx < 384; idx += 32) {
            int j = idx & 31, Gq = idx >> 5;
            int G = Gq >> 2, qq = Gq & 3;
            int jg = G * 32 + j;
            float bv = (G < 2) ? bhh[g * 96 + jg] : 0.0f;
            float vv[4];
            const int pos[4] = {2 * qq, 2 * qq + 1, 2 * qq + 8, 2 * qq + 9};
            #pragma unroll
            for (int k2 = 0; k2 < 4; k2++) {
                float vx = 0.0f;
                if (pos[k2] < OW) {
                    float v0 = gib[jg * 15 + ih0 * OW + pos[k2]];
                    float v1 = gib[jg * 15 + (ih0 + 1) * OW + pos[k2]];
                    vx = fmaf(fh, v1 - v0, v0) + bv;
                }
                vv[k2] = vx;
            }
            gp[Gq * 36 + j] = make_uint2(pack_h2(vv[0], vv[1]), pack_h2(vv[2], vv[3]));
        }
    }
    __syncthreads();

    const uint2* gpB = (OH == 1) ? (const uint2*)gbuf_raw
                                 : ((const uint2*)gbuf_raw + warp * 432);

    // OW==1: row-constant gi values in registers
    float gvr[2][2][2], gvz[2][2][2], gvn[2][2][2];
    if (OW == 1) {
        const float* gw = (const float*)gbuf_raw + warp * 96;
        #pragma unroll
        for (int e = 0; e < 2; e++)
            #pragma unroll
            for (int u = 0; u < 2; u++)
                #pragma unroll
                for (int d = 0; d < 2; d++) {
                    int jl = 16 * e + 8 * u + 2 * q + d;
                    gvr[e][u][d] = gw[jl];
                    gvz[e][u][d] = gw[32 + jl];
                    gvn[e][u][d] = gw[64 + jl];
                }
    }

    // bhh_n pairs for hn C-init
    float bn[2][2][2];
    #pragma unroll
    for (int e = 0; e < 2; e++)
        #pragma unroll
        for (int u = 0; u < 2; u++) {
            bn[e][u][0] = bhh[g * 96 + 64 + 16 * e + 8 * u + 2 * q];
            bn[e][u][1] = bhh[g * 96 + 64 + 16 * e + 8 * u + 2 * q + 1];
        }

    const float* xrow = x + ((size_t)(b * 128 + g * 16)) * HW + h * 128;
    float* outrow = out + ((size_t)b * 256 + g) * HW + h * 128;
    const float* xc0 = xrow + (size_t)(2 * q) * HW;
    const float* xc1 = xrow + (size_t)(2 * q + 1) * HW;
    const float* xc2 = xrow + (size_t)(2 * q + 8) * HW;
    const float* xc3 = xrow + (size_t)(2 * q + 9) * HW;

    for (int tile2 = 0; tile2 < 4; tile2++) {
        const int pxbase = tile2 * 32;

        // ---- A fragments: direct loads, fp16-packed ----
        uint32_t A[2][4];
        #pragma unroll
        for (int m = 0; m < 2; m++) {
            const int p0 = pxbase + m * 16 + p;
            float x00 = xc0[p0],     x10 = xc1[p0];
            float x01 = xc0[p0 + 8], x11 = xc1[p0 + 8];
            float x20 = xc2[p0],     x30 = xc3[p0];
            float x21 = xc2[p0 + 8], x31 = xc3[p0 + 8];
            A[m][0] = pack_h2(x00, x10);
            A[m][1] = pack_h2(x01, x11);
            A[m][2] = pack_h2(x20, x30);
            A[m][3] = pack_h2(x21, x31);
        }

        // ---- coef fragments ----
        uint32_t AC[2][4];
        if (OW > 1) {
            #pragma unroll
            for (int m = 0; m < 2; m++) {
                const int pe0 = pxbase + m * 16 + p, pe1 = pe0 + 8;
                float s0 = (float)(pe0 * (OW - 1)) * (1.0f / 127.0f);
                int j00 = (int)s0; if (j00 > OW - 2) j00 = OW - 2;
                float f0 = s0 - (float)j00;
                float s1 = (float)(pe1 * (OW - 1)) * (1.0f / 127.0f);
                int j01 = (int)s1; if (j01 > OW - 2) j01 = OW - 2;
                float f1 = s1 - (float)j01;
                AC[m][0] = pack_h2(coef_f(2 * q, j00, f0),     coef_f(2 * q + 1, j00, f0));
                AC[m][1] = pack_h2(coef_f(2 * q, j01, f1),     coef_f(2 * q + 1, j01, f1));
                AC[m][2] = pack_h2(coef_f(2 * q + 8, j00, f0), coef_f(2 * q + 9, j00, f0));
                AC[m][3] = pack_h2(coef_f(2 * q + 8, j01, f1), coef_f(2 * q + 9, j01, f1));
            }
        }

        #pragma unroll
        for (int eta = 0; eta < 2; eta++) {
            #pragma unroll
            for (int u = 0; u < 2; u++) {
                const int cb = 16 * eta + 8 * u + p;
                uint2 wr = Wh[q * 132 + cb];
                uint2 wz = Wh[q * 132 + 32 + cb];
                uint2 wn = Wh[q * 132 + 64 + cb];
                uint2 wc = Wh[q * 132 + 96 + cb];
                uint2 grB, gzB, gnB;
                if (OW > 1) {
                    grB = gpB[(0 * 4 + q) * 36 + cb];
                    gzB = gpB[(1 * 4 + q) * 36 + cb];
                    gnB = gpB[(2 * 4 + q) * 36 + cb];
                }

                #pragma unroll
                for (int m = 0; m < 2; m++) {
                    float aR[4], aZ[4], aN[4], aC[4], aG[4];
                    mmaf16_init(aR, A[m], wr.x, wr.y, 0.f, 0.f);
                    mmaf16_init(aZ, A[m], wz.x, wz.y, 0.f, 0.f);
                    mmaf16_init(aN, A[m], wn.x, wn.y, bn[eta][u][0], bn[eta][u][1]);
                    mmaf16_init(aC, A[m], wc.x, wc.y, 0.f, 0.f);
                    if (OW > 1) {
                        mmaf16_acc(aR, AC[m], grB.x, grB.y);
                        mmaf16_acc(aZ, AC[m], gzB.x, gzB.y);
                        mmaf16_init(aG, AC[m], gnB.x, gnB.y, 0.f, 0.f);
                    }

                    // ---- packed f16x2 epilogue: pairs (d=0,1) per pixel e ----
                    #pragma unroll
                    for (int e = 0; e < 2; e++) {
                        const int i0 = 2 * e;
                        const int jl = 16 * eta + 8 * u + 2 * q;
                        const int px = pxbase + m * 16 + p + e * 8;
                        uint32_t r2, z2, gn2;
                        if (OW == 1) {
                            r2 = pack_h2(gvr[eta][u][0] + aR[i0],
                                         gvr[eta][u][1] + aR[i0 + 1]);
                            z2 = pack_h2(gvz[eta][u][0] + aZ[i0],
                                         gvz[eta][u][1] + aZ[i0 + 1]);
                            gn2 = pack_h2(gvn[eta][u][0], gvn[eta][u][1]);
                        } else {
                            r2 = pack_h2(aR[i0], aR[i0 + 1]);
                            z2 = pack_h2(aZ[i0], aZ[i0 + 1]);
                            gn2 = pack_h2(aG[i0], aG[i0 + 1]);
                        }
                        r2 = sig2_u(r2);
                        z2 = sig2_u(z2);
                        uint32_t hn2 = pack_h2(aN[i0], aN[i0 + 1]);
                        uint32_t n2 = htanh2(hfma2_u(r2, hn2, gn2));
                        float2 nf = h2f(n2);
                        float2 zf = h2f(z2);
                        outrow[(size_t)(jl * 8) * HW + px] =
                            fmaf(zf.x, aC[i0] - nf.x, nf.x);
                        outrow[(size_t)((jl + 1) * 8) * HW + px] =
                            fmaf(zf.y, aC[i0 + 1] - nf.y, nf.y);
                    }
                }
            }
        }
    }
}

__global__ __launch_bounds__(128, 5) void main_kernel(
    const float* __restrict__ x, const float* __restrict__ Wcen,
    const float* __restrict__ bhh, float* __restrict__ out)
{
    __shared__ __align__(16) uint2 Wh[4 * 132];        // fp16 weight k-pairs
    __shared__ __align__(16) char gbuf_raw[4 * 432 * 8];  // per-warp Gh / gw

    const int g = blockIdx.y;
    const int b = blockIdx.x >> 5;
    const int t = threadIdx.x;

    // build Wh: [q][col] uint2 with k = {2q,2q+1} and {2q+8,2q+9}
    for (int idx = t; idx < 512; idx += 128) {
        int qq = idx >> 7, col = idx & 127;
        float w0, w1, w2, w3;
        if (col < 96) {
            const float* wf = &g_Wfold[(g * 96 + col) * 16];
            w0 = wf[2 * qq];     w1 = wf[2 * qq + 1];
            w2 = wf[2 * qq + 8]; w3 = wf[2 * qq + 9];
        } else {
            const float* wf = &Wcen[(g * 32 + col - 96) * 16];
            w0 = wf[2 * qq];     w1 = wf[2 * qq + 1];
            w2 = wf[2 * qq + 8]; w3 = wf[2 * qq + 9];
        }
        Wh[qq * 132 + col] = make_uint2(pack_h2(w0, w1), pack_h2(w2, w3));
    }
    // (__syncthreads happens inside run_group after gbuf build)

    switch (g >> 1) {
        case 0:  run_group<1, 11>(g, b, x, bhh, out, Wh, gbuf_raw); break;
        case 1:  run_group<11, 1>(g, b, x, bhh, out, Wh, gbuf_raw); break;
        case 2:  run_group<3, 5>(g, b, x, bhh, out, Wh, gbuf_raw); break;
        default: run_group<5, 3>(g, b, x, bhh, out, Wh, gbuf_raw); break;
    }
}

// ============================================================================
extern "C" void kernel_launch(void* const* d_in, const int* in_sizes, int n_in,
                              void* d_out, int out_size) {
    (void)in_sizes; (void)n_in; (void)out_size;
    const float* x    = (const float*)d_in[0];
    const float* Wcen = (const float*)d_in[1];
    const float* W0 = (const float*)d_in[2];  const float* b0 = (const float*)d_in[3];
    const float* W1 = (const float*)d_in[4];  const float* b1 = (const float*)d_in[5];
    const float* W2 = (const float*)d_in[6];  const float* b2 = (const float*)d_in[7];
    const float* W3 = (const float*)d_in[8];  const float* b3 = (const float*)d_in[9];
    const float* Wm  = (const float*)d_in[10];
    const float* Wih = (const float*)d_in[11];
    const float* Whh = (const float*)d_in[12];
    const float* bih = (const float*)d_in[13];
    const float* bhh = (const float*)d_in[14];
    float* out = (float*)d_out;

    pool_kernel<<<1024, 256>>>(x);
    gi_fold_kernel<<<264, 256>>>(W0, b0, W1, b1, W2, b2, W3, b3,
                                 Wm, Wih, bih, Whh, Wcen);
    main_kernel<<<dim3(256, 8), 128>>>(x, Wcen, bhh, out);
}

// round 15
// speedup vs baseline: 1.4941x; 1.0700x over previous
#include <cuda_runtime.h>
#include <stdint.h>

#define HW 16384   // 128*128

// ---- device scratch ----
__device__ float g_pool[4 * 8 * 128 * 15];   // [br][b][c][pos]
__device__ float g_Wfold[8 * 96 * 16];       // Whh @ W_center per group
__device__ float g_Gi[8 * 8 * 96 * 15];      // [b][g][o][pos] (includes bih)

// ---- helpers ----
// pack two f32 into f16x2: lower = first arg, upper = second arg
__device__ __forceinline__ uint32_t pack_h2(float lo, float hi) {
    uint32_t r; asm("cvt.rn.f16x2.f32 %0, %1, %2;" : "=r"(r) : "f"(hi), "f"(lo));
    return r;
}
__device__ __forceinline__ uint32_t htanh2(uint32_t x) {
    uint32_t y; asm("tanh.approx.f16x2 %0, %1;" : "=r"(y) : "r"(x)); return y;
}
__device__ __forceinline__ uint32_t hmul2_u(uint32_t a, uint32_t b) {
    uint32_t d; asm("mul.rn.f16x2 %0, %1, %2;" : "=r"(d) : "r"(a), "r"(b)); return d;
}
__device__ __forceinline__ uint32_t hfma2_u(uint32_t a, uint32_t b, uint32_t c) {
    uint32_t d; asm("fma.rn.f16x2 %0, %1, %2, %3;" : "=r"(d) : "r"(a), "r"(b), "r"(c));
    return d;
}
#define H05X2 0x38003800u   // {0.5h, 0.5h}
// sigmoid(x) = 0.5*tanh(0.5x)+0.5, packed
__device__ __forceinline__ uint32_t sig2_u(uint32_t x) {
    return hfma2_u(htanh2(hmul2_u(x, H05X2)), H05X2, H05X2);
}
__device__ __forceinline__ float2 h2f(uint32_t v) {
    float lo, hi;
    asm("{.reg .f16 l, h; mov.b32 {l, h}, %2; cvt.f32.f16 %0, l; cvt.f32.f16 %1, h;}"
        : "=f"(lo), "=f"(hi) : "r"(v));
    return make_float2(lo, hi);
}
__device__ __forceinline__ void mmaf16_acc(float d[4], const uint32_t a[4],
                                           uint32_t b0, uint32_t b1) {
    asm("mma.sync.aligned.m16n8k16.row.col.f32.f16.f16.f32 "
        "{%0,%1,%2,%3},{%4,%5,%6,%7},{%8,%9},{%0,%1,%2,%3};"
        : "+f"(d[0]), "+f"(d[1]), "+f"(d[2]), "+f"(d[3])
        : "r"(a[0]), "r"(a[1]), "r"(a[2]), "r"(a[3]), "r"(b0), "r"(b1));
}
__device__ __forceinline__ void mmaf16_init(float d[4], const uint32_t a[4],
                                            uint32_t b0, uint32_t b1,
                                            float c0, float c1) {
    asm("mma.sync.aligned.m16n8k16.row.col.f32.f16.f16.f32 "
        "{%0,%1,%2,%3},{%4,%5,%6,%7},{%8,%9},{%10,%11,%10,%11};"
        : "=f"(d[0]), "=f"(d[1]), "=f"(d[2]), "=f"(d[3])
        : "r"(a[0]), "r"(a[1]), "r"(a[2]), "r"(a[3]), "r"(b0), "r"(b1),
          "f"(c0), "f"(c1));
}
__device__ __forceinline__ float coef_f(int pos, int j0, float fw) {
    return (pos == j0) ? (1.0f - fw) : ((pos == j0 + 1) ? fw : 0.0f);
}

// ============================================================================
// K1: adaptive pools (proven R8 version). Block per (b,c), 256 threads =
// 2 per column (h halves); compile-time bin membership via full unroll.
// ============================================================================
#define POOL_BODY(hconst)                                                      \
    {                                                                          \
        const int hv = (hconst);                                               \
        float v = tile[hv * 128 + col];                                        \
        a0 += v;                                                               \
        {                                                                      \
            const int pb = (hv * 11) >> 7;                                     \
            a1[pb] += v;                                                       \
            if (pb + 1 < 11 && hv == ((pb + 1) * 128) / 11 &&                  \
                (((pb + 1) * 128) % 11) != 0) a1[pb + 1] += v;                 \
        }                                                                      \
        {                                                                      \
            const int pb = (hv * 3) >> 7;                                      \
            a2[pb] += v;                                                       \
            if (pb + 1 < 3 && hv == ((pb + 1) * 128) / 3 &&                    \
                (((pb + 1) * 128) % 3) != 0) a2[pb + 1] += v;                  \
        }                                                                      \
        {                                                                      \
            const int pb = (hv * 5) >> 7;                                      \
            a3[pb] += v;                                                       \
            if (pb + 1 < 5 && hv == ((pb + 1) * 128) / 5 &&                    \
                (((pb + 1) * 128) % 5) != 0) a3[pb + 1] += v;                  \
        }                                                                      \
    }

__global__ __launch_bounds__(256) void pool_kernel(const float* __restrict__ x) {
    const int bc = blockIdx.x;
    const int b = bc >> 7, c = bc & 127;
    const float* tile = x + (size_t)bc * HW;
    const int col = threadIdx.x & 127, hh = threadIdx.x >> 7;

    float a0 = 0.0f;
    float a1[11], a2[3], a3[5];
    #pragma unroll
    for (int i = 0; i < 11; i++) a1[i] = 0.0f;
    #pragma unroll
    for (int i = 0; i < 3; i++) a2[i] = 0.0f;
    #pragma unroll
    for (int i = 0; i < 5; i++) a3[i] = 0.0f;

    if (hh == 0) {
        #pragma unroll
        for (int h = 0; h < 64; h++) POOL_BODY(h)
    } else {
        #pragma unroll
        for (int h = 64; h < 128; h++) POOL_BODY(h)
    }

    __shared__ float cs[2][20][128];
    cs[hh][0][col] = a0;
    #pragma unroll
    for (int i = 0; i < 11; i++) cs[hh][1 + i][col] = a1[i];
    #pragma unroll
    for (int i = 0; i < 3; i++) cs[hh][12 + i][col] = a2[i];
    #pragma unroll
    for (int i = 0; i < 5; i++) cs[hh][15 + i][col] = a3[i];
    __syncthreads();

    const int warp = threadIdx.x >> 5, lane = threadIdx.x & 31;
    for (int oi = warp; oi < 52; oi += 8) {
        int br, pos, row, ws, we, hs, he;
        if (oi < 11) {
            br = 0; pos = oi; row = 0;
            hs = 0; he = 128;
            ws = (pos * 128) / 11; we = ((pos + 1) * 128 + 10) / 11;
        } else if (oi < 22) {
            br = 1; pos = oi - 11; row = 1 + pos;
            ws = 0; we = 128;
            hs = (pos * 128) / 11; he = ((pos + 1) * 128 + 10) / 11;
        } else if (oi < 37) {
            br = 2; pos = oi - 22;
            int i = pos / 5, jj = pos % 5;
            row = 12 + i;
            hs = (i * 128) / 3;  he = ((i + 1) * 128 + 2) / 3;
            ws = (jj * 128) / 5; we = ((jj + 1) * 128 + 4) / 5;
        } else {
            br = 3; pos = oi - 37;
            int i = pos / 3, jj = pos % 3;
            row = 15 + i;
            hs = (i * 128) / 5;  he = ((i + 1) * 128 + 4) / 5;
            ws = (jj * 128) / 3; we = ((jj + 1) * 128 + 2) / 3;
        }
        float s = 0.0f;
        for (int w = ws + lane; w < we; w += 32)
            s += cs[0][row][w] + cs[1][row][w];
        #pragma unroll
        for (int off = 16; off; off >>= 1) s += __shfl_down_sync(0xffffffffu, s, off);
        if (lane == 0)
            g_pool[((br * 8 + b) * 128 + c) * 15 + pos] =
                s / (float)((he - hs) * (we - ws));
    }
}

// ============================================================================
// K2: fused branch-linear + merge + Wih -> Gi (blocks 0..255, 4 per (b,g)),
//     plus Wfold = Whh @ W_center (blocks 256..263).
// ============================================================================
__global__ __launch_bounds__(256) void gi_fold_kernel(
    const float* __restrict__ W0, const float* __restrict__ b0,
    const float* __restrict__ W1, const float* __restrict__ b1,
    const float* __restrict__ W2, const float* __restrict__ b2,
    const float* __restrict__ W3, const float* __restrict__ b3,
    const float* __restrict__ Wm, const float* __restrict__ Wih,
    const float* __restrict__ bih,
    const float* __restrict__ Whh, const float* __restrict__ Wcen)
{
    const int blk = blockIdx.x;
    const int t = threadIdx.x;

    if (blk >= 256) {              // fold part
        int g = blk - 256;
        if (t < 96) {
            int o = t;
            #pragma unroll 4
            for (int i = 0; i < 16; i++) {
                float s = 0.0f;
                #pragma unroll
                for (int hh = 0; hh < 32; hh++)
                    s = fmaf(Whh[(g * 96 + o) * 32 + hh], Wcen[(g * 32 + hh) * 16 + i], s);
                g_Wfold[(g * 96 + o) * 16 + i] = s;
            }
        }
        return;
    }

    const int b = blk >> 5, g = (blk >> 2) & 7, quarter = blk & 3;
    const int br = g >> 1;
    const int GS = (br < 2) ? 11 : 15;
    const float* Ws[4] = {W0, W1, W2, W3};
    const float* bs[4] = {b0, b1, b2, b3};
    const float* W = Ws[br];
    const float* bias = bs[br];
    const int c0 = 64 * (g & 1);

    __shared__ float q[64 * 15];
    __shared__ float Bs[32 * 15];

    for (int idx = t; idx < 64 * GS; idx += 256) {
        int cc = idx / GS, m = idx - cc * GS;
        const float* src = g_pool + ((br * 8 + b) * 128 + c0 + cc) * 15;
        float s = bias[m];
        for (int d = 0; d < GS; d++) s = fmaf(W[m * GS + d], src[d], s);
        q[cc * GS + m] = s;
    }
    __syncthreads();

    for (int idx = t; idx < 32 * GS; idx += 256) {
        int f = idx / GS, pos = idx - f * GS;
        int i = 16 * g + (f >> 1), jm = f & 1;
        const float* qb = q + (4 * (f >> 1)) * GS + pos;
        float s = 0.0f;
        #pragma unroll
        for (int k = 0; k < 4; k++)
            s = fmaf(Wm[(i * 2 + jm) * 4 + k], qb[k * GS], s);
        Bs[f * GS + pos] = s;
    }
    __syncthreads();

    const int obase = quarter * 24;
    for (int idx = t; idx < 24 * GS; idx += 256) {
        int o = obase + idx / GS, pos = idx % GS;
        float s = bih[g * 96 + o];
        #pragma unroll 8
        for (int f = 0; f < 32; f++)
            s = fmaf(Wih[(g * 96 + o) * 32 + f], Bs[f * GS + pos], s);
        g_Gi[((b * 8 + g) * 96 + o) * 15 + pos] = s;
    }
}

// ============================================================================
// K3: main kernel (R14 structure; __stcs streaming output stores so x stays
// L2-resident for main's reads and across graph replays).
// fp16 m16n8k16 mma; w-interp folded as extra k16 mma; direct-LDG A frags;
// f16x2-packed activations.
// grid (256, 8): g = blockIdx.y; b = blockIdx.x>>5; warp = one image row.
// ============================================================================
template<int OH, int OW>
__device__ __forceinline__ void run_group(
    int g, int b, const float* __restrict__ x, const float* __restrict__ bhh,
    float* __restrict__ out, const uint2* Wh, char* gbuf_raw)
{
    const int t = threadIdx.x;
    const int warp = t >> 5, lane = t & 31;
    const int p = lane >> 2, q = lane & 3;
    const int h = ((blockIdx.x & 31) << 2) + warp;
    const float* gib = g_Gi + (size_t)((b * 8 + g) * 96) * 15;

    // ---- build interp structures ----
    if (OW == 1) {
        float* gw = (float*)gbuf_raw + warp * 96;
        float src = (float)(h * (OH - 1)) * (1.0f / 127.0f);
        int ih0 = (int)src; if (ih0 > OH - 2) ih0 = OH - 2;
        float fh = src - (float)ih0;
        for (int j = lane; j < 96; j += 32) {
            float v0 = gib[j * 15 + ih0];
            float v1 = gib[j * 15 + ih0 + 1];
            float v = fmaf(fh, v1 - v0, v0);
            if (j < 64) v += bhh[g * 96 + j];
            gw[j] = v;
        }
    } else if (OH == 1) {
        uint2* gp = (uint2*)gbuf_raw;
        for (int idx = t; idx < 384; idx += 128) {
            int j = idx & 31, Gq = idx >> 5;
            int G = Gq >> 2, qq = Gq & 3;
            int jg = G * 32 + j;
            float bv = (G < 2) ? bhh[g * 96 + jg] : 0.0f;
            float v0 = (2 * qq     < OW) ? gib[jg * 15 + 2 * qq]     + bv : 0.0f;
            float v1 = (2 * qq + 1 < OW) ? gib[jg * 15 + 2 * qq + 1] + bv : 0.0f;
            float v2 = (2 * qq + 8 < OW) ? gib[jg * 15 + 2 * qq + 8] + bv : 0.0f;
            float v3 = (2 * qq + 9 < OW) ? gib[jg * 15 + 2 * qq + 9] + bv : 0.0f;
            gp[Gq * 36 + j] = make_uint2(pack_h2(v0, v1), pack_h2(v2, v3));
        }
    } else {
        uint2* gp = (uint2*)gbuf_raw + warp * 432;
        float src = (float)(h * (OH - 1)) * (1.0f / 127.0f);
        int ih0 = (int)src; if (ih0 > OH - 2) ih0 = OH - 2;
        float fh = src - (float)ih0;
        for (int idx = lane; idx < 384; idx += 32) {
            int j = idx & 31, Gq = idx >> 5;
            int G = Gq >> 2, qq = Gq & 3;
            int jg = G * 32 + j;
            float bv = (G < 2) ? bhh[g * 96 + jg] : 0.0f;
            float vv[4];
            const int pos[4] = {2 * qq, 2 * qq + 1, 2 * qq + 8, 2 * qq + 9};
            #pragma unroll
            for (int k2 = 0; k2 < 4; k2++) {
                float vx = 0.0f;
                if (pos[k2] < OW) {
                    float v0 = gib[jg * 15 + ih0 * OW + pos[k2]];
                    float v1 = gib[jg * 15 + (ih0 + 1) * OW + pos[k2]];
                    vx = fmaf(fh, v1 - v0, v0) + bv;
                }
                vv[k2] = vx;
            }
            gp[Gq * 36 + j] = make_uint2(pack_h2(vv[0], vv[1]), pack_h2(vv[2], vv[3]));
        }
    }
    __syncthreads();

    const uint2* gpB = (OH == 1) ? (const uint2*)gbuf_raw
                                 : ((const uint2*)gbuf_raw + warp * 432);

    // OW==1: row-constant gi values in registers
    float gvr[2][2][2], gvz[2][2][2], gvn[2][2][2];
    if (OW == 1) {
        const float* gw = (const float*)gbuf_raw + warp * 96;
        #pragma unroll
        for (int e = 0; e < 2; e++)
            #pragma unroll
            for (int u = 0; u < 2; u++)
                #pragma unroll
                for (int d = 0; d < 2; d++) {
                    int jl = 16 * e + 8 * u + 2 * q + d;
                    gvr[e][u][d] = gw[jl];
                    gvz[e][u][d] = gw[32 + jl];
                    gvn[e][u][d] = gw[64 + jl];
                }
    }

    // bhh_n pairs for hn C-init
    float bn[2][2][2];
    #pragma unroll
    for (int e = 0; e < 2; e++)
        #pragma unroll
        for (int u = 0; u < 2; u++) {
            bn[e][u][0] = bhh[g * 96 + 64 + 16 * e + 8 * u + 2 * q];
            bn[e][u][1] = bhh[g * 96 + 64 + 16 * e + 8 * u + 2 * q + 1];
        }

    const float* xrow = x + ((size_t)(b * 128 + g * 16)) * HW + h * 128;
    float* outrow = out + ((size_t)b * 256 + g) * HW + h * 128;
    const float* xc0 = xrow + (size_t)(2 * q) * HW;
    const float* xc1 = xrow + (size_t)(2 * q + 1) * HW;
    const float* xc2 = xrow + (size_t)(2 * q + 8) * HW;
    const float* xc3 = xrow + (size_t)(2 * q + 9) * HW;

    for (int tile2 = 0; tile2 < 4; tile2++) {
        const int pxbase = tile2 * 32;

        // ---- A fragments: direct loads, fp16-packed ----
        uint32_t A[2][4];
        #pragma unroll
        for (int m = 0; m < 2; m++) {
            const int p0 = pxbase + m * 16 + p;
            float x00 = xc0[p0],     x10 = xc1[p0];
            float x01 = xc0[p0 + 8], x11 = xc1[p0 + 8];
            float x20 = xc2[p0],     x30 = xc3[p0];
            float x21 = xc2[p0 + 8], x31 = xc3[p0 + 8];
            A[m][0] = pack_h2(x00, x10);
            A[m][1] = pack_h2(x01, x11);
            A[m][2] = pack_h2(x20, x30);
            A[m][3] = pack_h2(x21, x31);
        }

        // ---- coef fragments ----
        uint32_t AC[2][4];
        if (OW > 1) {
            #pragma unroll
            for (int m = 0; m < 2; m++) {
                const int pe0 = pxbase + m * 16 + p, pe1 = pe0 + 8;
                float s0 = (float)(pe0 * (OW - 1)) * (1.0f / 127.0f);
                int j00 = (int)s0; if (j00 > OW - 2) j00 = OW - 2;
                float f0 = s0 - (float)j00;
                float s1 = (float)(pe1 * (OW - 1)) * (1.0f / 127.0f);
                int j01 = (int)s1; if (j01 > OW - 2) j01 = OW - 2;
                float f1 = s1 - (float)j01;
                AC[m][0] = pack_h2(coef_f(2 * q, j00, f0),     coef_f(2 * q + 1, j00, f0));
                AC[m][1] = pack_h2(coef_f(2 * q, j01, f1),     coef_f(2 * q + 1, j01, f1));
                AC[m][2] = pack_h2(coef_f(2 * q + 8, j00, f0), coef_f(2 * q + 9, j00, f0));
                AC[m][3] = pack_h2(coef_f(2 * q + 8, j01, f1), coef_f(2 * q + 9, j01, f1));
            }
        }

        #pragma unroll
        for (int eta = 0; eta < 2; eta++) {
            #pragma unroll
            for (int u = 0; u < 2; u++) {
                const int cb = 16 * eta + 8 * u + p;
                uint2 wr = Wh[q * 132 + cb];
                uint2 wz = Wh[q * 132 + 32 + cb];
                uint2 wn = Wh[q * 132 + 64 + cb];
                uint2 wc = Wh[q * 132 + 96 + cb];
                uint2 grB, gzB, gnB;
                if (OW > 1) {
                    grB = gpB[(0 * 4 + q) * 36 + cb];
                    gzB = gpB[(1 * 4 + q) * 36 + cb];
                    gnB = gpB[(2 * 4 + q) * 36 + cb];
                }

                #pragma unroll
                for (int m = 0; m < 2; m++) {
                    float aR[4], aZ[4], aN[4], aC[4], aG[4];
                    mmaf16_init(aR, A[m], wr.x, wr.y, 0.f, 0.f);
                    mmaf16_init(aZ, A[m], wz.x, wz.y, 0.f, 0.f);
                    mmaf16_init(aN, A[m], wn.x, wn.y, bn[eta][u][0], bn[eta][u][1]);
                    mmaf16_init(aC, A[m], wc.x, wc.y, 0.f, 0.f);
                    if (OW > 1) {
                        mmaf16_acc(aR, AC[m], grB.x, grB.y);
                        mmaf16_acc(aZ, AC[m], gzB.x, gzB.y);
                        mmaf16_init(aG, AC[m], gnB.x, gnB.y, 0.f, 0.f);
                    }

                    // ---- packed f16x2 epilogue: pairs (d=0,1) per pixel e ----
                    #pragma unroll
                    for (int e = 0; e < 2; e++) {
                        const int i0 = 2 * e;
                        const int jl = 16 * eta + 8 * u + 2 * q;
                        const int px = pxbase + m * 16 + p + e * 8;
                        uint32_t r2, z2, gn2;
                        if (OW == 1) {
                            r2 = pack_h2(gvr[eta][u][0] + aR[i0],
                                         gvr[eta][u][1] + aR[i0 + 1]);
                            z2 = pack_h2(gvz[eta][u][0] + aZ[i0],
                                         gvz[eta][u][1] + aZ[i0 + 1]);
                            gn2 = pack_h2(gvn[eta][u][0], gvn[eta][u][1]);
                        } else {
                            r2 = pack_h2(aR[i0], aR[i0 + 1]);
                            z2 = pack_h2(aZ[i0], aZ[i0 + 1]);
                            gn2 = pack_h2(aG[i0], aG[i0 + 1]);
                        }
                        r2 = sig2_u(r2);
                        z2 = sig2_u(z2);
                        uint32_t hn2 = pack_h2(aN[i0], aN[i0 + 1]);
                        uint32_t n2 = htanh2(hfma2_u(r2, hn2, gn2));
                        float2 nf = h2f(n2);
                        float2 zf = h2f(z2);
                        __stcs(outrow + (size_t)(jl * 8) * HW + px,
                               fmaf(zf.x, aC[i0] - nf.x, nf.x));
                        __stcs(outrow + (size_t)((jl + 1) * 8) * HW + px,
                               fmaf(zf.y, aC[i0 + 1] - nf.y, nf.y));
                    }
                }
            }
        }
    }
}

__global__ __launch_bounds__(128, 5) void main_kernel(
    const float* __restrict__ x, const float* __restrict__ Wcen,
    const float* __restrict__ bhh, float* __restrict__ out)
{
    __shared__ __align__(16) uint2 Wh[4 * 132];        // fp16 weight k-pairs
    __shared__ __align__(16) char gbuf_raw[4 * 432 * 8];  // per-warp Gh / gw

    const int g = blockIdx.y;
    const int b = blockIdx.x >> 5;
    const int t = threadIdx.x;

    // build Wh: [q][col] uint2 with k = {2q,2q+1} and {2q+8,2q+9}
    for (int idx = t; idx < 512; idx += 128) {
        int qq = idx >> 7, col = idx & 127;
        float w0, w1, w2, w3;
        if (col < 96) {
            const float* wf = &g_Wfold[(g * 96 + col) * 16];
            w0 = wf[2 * qq];     w1 = wf[2 * qq + 1];
            w2 = wf[2 * qq + 8]; w3 = wf[2 * qq + 9];
        } else {
            const float* wf = &Wcen[(g * 32 + col - 96) * 16];
            w0 = wf[2 * qq];     w1 = wf[2 * qq + 1];
            w2 = wf[2 * qq + 8]; w3 = wf[2 * qq + 9];
        }
        Wh[qq * 132 + col] = make_uint2(pack_h2(w0, w1), pack_h2(w2, w3));
    }
    // (__syncthreads happens inside run_group after gbuf build)

    switch (g >> 1) {
        case 0:  run_group<1, 11>(g, b, x, bhh, out, Wh, gbuf_raw); break;
        case 1:  run_group<11, 1>(g, b, x, bhh, out, Wh, gbuf_raw); break;
        case 2:  run_group<3, 5>(g, b, x, bhh, out, Wh, gbuf_raw); break;
        default: run_group<5, 3>(g, b, x, bhh, out, Wh, gbuf_raw); break;
    }
}

// ============================================================================
extern "C" void kernel_launch(void* const* d_in, const int* in_sizes, int n_in,
                              void* d_out, int out_size) {
    (void)in_sizes; (void)n_in; (void)out_size;
    const float* x    = (const float*)d_in[0];
    const float* Wcen = (const float*)d_in[1];
    const float* W0 = (const float*)d_in[2];  const float* b0 = (const float*)d_in[3];
    const float* W1 = (const float*)d_in[4];  const float* b1 = (const float*)d_in[5];
    const float* W2 = (const float*)d_in[6];  const float* b2 = (const float*)d_in[7];
    const float* W3 = (const float*)d_in[8];  const float* b3 = (const float*)d_in[9];
    const float* Wm  = (const float*)d_in[10];
    const float* Wih = (const float*)d_in[11];
    const float* Whh = (const float*)d_in[12];
    const float* bih = (const float*)d_in[13];
    const float* bhh = (const float*)d_in[14];
    float* out = (float*)d_out;

    pool_kernel<<<1024, 256>>>(x);
    gi_fold_kernel<<<264, 256>>>(W0, b0, W1, b1, W2, b2, W3, b3,
                                 Wm, Wih, bih, Whh, Wcen);
    main_kernel<<<dim3(256, 8), 128>>>(x, Wcen, bhh, out);
}